// round 10
// baseline (speedup 1.0000x reference)
#include <cuda_runtime.h>
#include <cuda_bf16.h>
#include <mma.h>
#include <math.h>
#include <stdint.h>

using namespace nvcuda;

#define N_NODES 16000
#define N_EDGES 256000
#define D 128
#define H 4
#define G3 (3*D)        // 384
#define HD (H*D)        // 512
#define ALPHA 0.2f

// ---------------- static scratch ----------------
__device__ float g_Wh[N_NODES * H * D];
__device__ float g_ssrc[N_NODES * H];
__device__ float g_sdst[N_NODES * H];
__device__ float g_hprime[N_NODES * H * D];   // x reshaped (N, 512)
__device__ float g_gi[N_NODES * G3];
__device__ float g_gh[N_NODES * G3];
__device__ float g_WT[H * D * D];             // W transposed: [h][e][d]
__device__ int   g_deg[N_NODES];
__device__ int   g_fill[N_NODES];
__device__ int   g_rowptr[N_NODES + 1];
__device__ int   g_csr[N_EDGES];

// split fp32 -> bf16 hi + bf16 lo
__device__ __forceinline__ void split1(float x, __nv_bfloat16& hi, __nv_bfloat16& lo) {
    hi = __float2bfloat16_rn(x);
    lo = __float2bfloat16_rn(x - __bfloat162float(hi));
}

// ---------------- wmma GEMM with register prefetch pipeline ----------------
// C[128 x 128-tile] = A[M,K] @ B[NB,K]^T, 3-term bf16 split (fp32 accum).
// 256 threads = 8 warps, warp grid 4(m) x 2(n), warp tile 32x64.
template<int KTOT>
__device__ __forceinline__ void tc_gemm_wmma(const float* __restrict__ A,
                                             const float* __restrict__ B,
                                             float* __restrict__ C, int ldC) {
    __shared__ __nv_bfloat16 Ah[128][40];
    __shared__ __nv_bfloat16 Al[128][40];
    __shared__ __nv_bfloat16 Bh[128][40];
    __shared__ __nv_bfloat16 Bl[128][40];

    int tid = threadIdx.x;
    int wid = tid >> 5;
    int warpM = wid >> 1;          // 0..3
    int warpN = wid & 1;           // 0..1
    int row0 = blockIdx.x * 128;

    wmma::fragment<wmma::accumulator, 16, 16, 16, float> acc[2][4];
    #pragma unroll
    for (int i = 0; i < 2; i++)
        #pragma unroll
        for (int j = 0; j < 4; j++)
            wmma::fill_fragment(acc[i][j], 0.0f);

    const int KC = KTOT / 32;
    float4 pa[4], pb[4];

    // prefetch chunk 0
    #pragma unroll
    for (int it = 0; it < 4; it++) {
        int idx = tid + it * 256;
        int r = idx >> 3, c4 = (idx & 7) * 4;
        pa[it] = *(const float4*)&A[(size_t)(row0 + r) * KTOT + c4];
        pb[it] = *(const float4*)&B[(size_t)r * KTOT + c4];
    }

    #pragma unroll 1
    for (int c = 0; c < KC; c++) {
        // convert regs -> smem
        #pragma unroll
        for (int it = 0; it < 4; it++) {
            int idx = tid + it * 256;
            int r = idx >> 3, c4 = (idx & 7) * 4;
            split1(pa[it].x, Ah[r][c4 + 0], Al[r][c4 + 0]);
            split1(pa[it].y, Ah[r][c4 + 1], Al[r][c4 + 1]);
            split1(pa[it].z, Ah[r][c4 + 2], Al[r][c4 + 2]);
            split1(pa[it].w, Ah[r][c4 + 3], Al[r][c4 + 3]);
            split1(pb[it].x, Bh[r][c4 + 0], Bl[r][c4 + 0]);
            split1(pb[it].y, Bh[r][c4 + 1], Bl[r][c4 + 1]);
            split1(pb[it].z, Bh[r][c4 + 2], Bl[r][c4 + 2]);
            split1(pb[it].w, Bh[r][c4 + 3], Bl[r][c4 + 3]);
        }
        __syncthreads();

        // prefetch next chunk (LDGs overlap the MMA phase below)
        if (c + 1 < KC) {
            #pragma unroll
            for (int it = 0; it < 4; it++) {
                int idx = tid + it * 256;
                int r = idx >> 3, c4 = (idx & 7) * 4;
                pa[it] = *(const float4*)&A[(size_t)(row0 + r) * KTOT + (c + 1) * 32 + c4];
                pb[it] = *(const float4*)&B[(size_t)r * KTOT + (c + 1) * 32 + c4];
            }
        }

        // MMA phase on chunk c
        #pragma unroll
        for (int ks = 0; ks < 2; ks++) {
            wmma::fragment<wmma::matrix_a, 16, 16, 16, __nv_bfloat16, wmma::row_major> a_hi[2], a_lo[2];
            #pragma unroll
            for (int fm = 0; fm < 2; fm++) {
                wmma::load_matrix_sync(a_hi[fm], &Ah[warpM * 32 + fm * 16][ks * 16], 40);
                wmma::load_matrix_sync(a_lo[fm], &Al[warpM * 32 + fm * 16][ks * 16], 40);
            }
            #pragma unroll
            for (int fn = 0; fn < 4; fn++) {
                wmma::fragment<wmma::matrix_b, 16, 16, 16, __nv_bfloat16, wmma::col_major> b_hi, b_lo;
                wmma::load_matrix_sync(b_hi, &Bh[warpN * 64 + fn * 16][ks * 16], 40);
                wmma::load_matrix_sync(b_lo, &Bl[warpN * 64 + fn * 16][ks * 16], 40);
                #pragma unroll
                for (int fm = 0; fm < 2; fm++) {
                    wmma::mma_sync(acc[fm][fn], a_hi[fm], b_hi, acc[fm][fn]);
                    wmma::mma_sync(acc[fm][fn], a_hi[fm], b_lo, acc[fm][fn]);
                    wmma::mma_sync(acc[fm][fn], a_lo[fm], b_hi, acc[fm][fn]);
                }
            }
        }
        __syncthreads();
    }

    // epilogue: direct store (bias handled downstream)
    #pragma unroll
    for (int fm = 0; fm < 2; fm++) {
        int row = row0 + warpM * 32 + fm * 16;
        #pragma unroll
        for (int fn = 0; fn < 4; fn++) {
            int col = warpN * 64 + fn * 16;
            wmma::store_matrix_sync(&C[(size_t)row * ldC + col], acc[fm][fn], ldC, wmma::mem_row_major);
        }
    }
}

// Wh[n, head*128 .. ] = h @ W[head]^T' : B = g_WT[head] (128x128, [e][d])
__global__ void __launch_bounds__(256) k_wh_tc(const float* __restrict__ hin) {
    int head = blockIdx.y;
    tc_gemm_wmma<128>(hin, &g_WT[head << 14], &g_Wh[head << 7], HD);
}
// gi = x @ W_ih^T : A = g_hprime (N x 512), B tile = W_ih + col0*512
__global__ void __launch_bounds__(256) k_gi_tc(const float* __restrict__ Wih) {
    int col0 = blockIdx.y * 128;
    tc_gemm_wmma<HD>(g_hprime, Wih + (size_t)col0 * HD, g_gi + col0, G3);
}
// gh = h @ W_hh^T
__global__ void __launch_bounds__(256) k_gh_tc(const float* __restrict__ hin,
                                               const float* __restrict__ Whh) {
    int col0 = blockIdx.y * 128;
    tc_gemm_wmma<D>(hin, Whh + (size_t)col0 * D, g_gh + col0, G3);
}

// ---------------- W transpose: g_WT[h][e][d] = W[h][d][e] ----------------
__global__ void k_transposeW(const float* __restrict__ W) {
    int idx = blockIdx.x * blockDim.x + threadIdx.x;
    if (idx < H * D * D) {
        int h = idx >> 14, rem = idx & 16383, d = rem >> 7, e = rem & 127;
        g_WT[(h << 14) + (e << 7) + d] = W[idx];
    }
}

// ---------------- CSR build ----------------
__global__ void k_init_counts() {
    int i = blockIdx.x * blockDim.x + threadIdx.x;
    if (i < N_NODES) { g_deg[i] = 0; g_fill[i] = 0; }
}
__global__ void k_count(const int* __restrict__ dst) {
    int e = blockIdx.x * blockDim.x + threadIdx.x;
    if (e < N_EDGES) atomicAdd(&g_deg[dst[e]], 1);
}

// fast single-block scan: 1024 thr x 16 elems, warp-shuffle based
__global__ void __launch_bounds__(1024) k_scan() {
    __shared__ int wsum[32];
    int t = threadIdx.x;
    int lane = t & 31, warp = t >> 5;
    int base = t * 16;
    int v[16];
    int s = 0;
    #pragma unroll
    for (int i = 0; i < 16; i++) {
        int idx = base + i;
        int x = (idx < N_NODES) ? g_deg[idx] : 0;
        v[i] = s;              // exclusive prefix within thread
        s += x;
    }
    // inclusive warp scan of per-thread sums
    int incl = s;
    #pragma unroll
    for (int o = 1; o < 32; o <<= 1) {
        int y = __shfl_up_sync(0xffffffffu, incl, o);
        if (lane >= o) incl += y;
    }
    if (lane == 31) wsum[warp] = incl;
    __syncthreads();
    if (warp == 0) {
        int w = wsum[lane];
        #pragma unroll
        for (int o = 1; o < 32; o <<= 1) {
            int y = __shfl_up_sync(0xffffffffu, w, o);
            if (lane >= o) w += y;
        }
        wsum[lane] = w;        // inclusive warp sums
    }
    __syncthreads();
    int warpoff = (warp > 0) ? wsum[warp - 1] : 0;
    int throff = warpoff + (incl - s);   // exclusive across threads
    #pragma unroll
    for (int i = 0; i < 16; i++) {
        int idx = base + i;
        if (idx < N_NODES) g_rowptr[idx] = throff + v[i];
    }
    if (t == 1023) g_rowptr[N_NODES] = wsum[31];
}

__global__ void k_fill(const int* __restrict__ dst) {
    int e = blockIdx.x * blockDim.x + threadIdx.x;
    if (e < N_EDGES) {
        int d = dst[e];
        int pos = g_rowptr[d] + atomicAdd(&g_fill[d], 1);
        g_csr[pos] = e;
    }
}

// ---------------- scores ----------------
__global__ void __launch_bounds__(256) k_scores(const float* __restrict__ a) {
    int tid = threadIdx.x, lane = tid & 31, warp = tid >> 5;
    int w = blockIdx.x * 8 + warp;
    int head = w & (H - 1);
    float4 wv = ((const float4*)(g_Wh + w * D))[lane];
    float4 a1 = *(const float4*)&a[head * (2 * D) + lane * 4];
    float4 a2 = *(const float4*)&a[head * (2 * D) + D + lane * 4];
    float d1 = wv.x * a1.x + wv.y * a1.y + wv.z * a1.z + wv.w * a1.w;
    float d2 = wv.x * a2.x + wv.y * a2.y + wv.z * a2.z + wv.w * a2.w;
    #pragma unroll
    for (int o = 16; o; o >>= 1) {
        d1 += __shfl_xor_sync(0xffffffffu, d1, o);
        d2 += __shfl_xor_sync(0xffffffffu, d2, o);
    }
    if (lane == 0) { g_ssrc[w] = d1; g_sdst[w] = d2; }
}

// ---------------- softmax + aggregate ----------------
__global__ void __launch_bounds__(128) k_agg(const int* __restrict__ src) {
    int n = blockIdx.x;
    int head = threadIdx.x >> 5;
    int lane = threadIdx.x & 31;
    int start = g_rowptr[n], end = g_rowptr[n + 1];
    float4 acc = make_float4(0.f, 0.f, 0.f, 0.f);
    if (end > start) {
        float sd = g_sdst[n * H + head];
        float m = -1e30f;
        for (int j = start + lane; j < end; j += 32) {
            int s = src[g_csr[j]];
            float v = g_ssrc[s * H + head] + sd;
            v = v >= 0.f ? v : ALPHA * v;
            m = fmaxf(m, v);
        }
        #pragma unroll
        for (int o = 16; o; o >>= 1) m = fmaxf(m, __shfl_xor_sync(0xffffffffu, m, o));
        float sum = 0.f;
        for (int j = start + lane; j < end; j += 32) {
            int s = src[g_csr[j]];
            float v = g_ssrc[s * H + head] + sd;
            v = v >= 0.f ? v : ALPHA * v;
            sum += __expf(v - m);
        }
        #pragma unroll
        for (int o = 16; o; o >>= 1) sum += __shfl_xor_sync(0xffffffffu, sum, o);
        float inv = 1.0f / sum;
        for (int j = start; j < end; j++) {
            int s = src[g_csr[j]];
            float v = g_ssrc[s * H + head] + sd;
            v = v >= 0.f ? v : ALPHA * v;
            float att = __expf(v - m) * inv;
            float4 wv = ((const float4*)(g_Wh + (s * H + head) * D))[lane];
            acc.x += att * wv.x; acc.y += att * wv.y;
            acc.z += att * wv.z; acc.w += att * wv.w;
        }
    }
    ((float4*)(g_hprime + (n * H + head) * D))[lane] = acc;
}

// ---------------- GRU elementwise (bias folded here) ----------------
__global__ void __launch_bounds__(256) k_gru(const float* __restrict__ hin,
                                             const float* __restrict__ bih,
                                             const float* __restrict__ bhh,
                                             float* __restrict__ out) {
    int idx = blockIdx.x * blockDim.x + threadIdx.x;
    if (idx >= N_NODES * D) return;
    int n = idx >> 7;
    int d = idx & (D - 1);
    float ir = g_gi[n * G3 + d]          + bih[d];
    float iz = g_gi[n * G3 + D + d]      + bih[D + d];
    float in_ = g_gi[n * G3 + 2 * D + d] + bih[2 * D + d];
    float hr = g_gh[n * G3 + d]          + bhh[d];
    float hz = g_gh[n * G3 + D + d]      + bhh[D + d];
    float hn = g_gh[n * G3 + 2 * D + d]  + bhh[2 * D + d];
    float r = 1.0f / (1.0f + __expf(-(ir + hr)));
    float z = 1.0f / (1.0f + __expf(-(iz + hz)));
    float nv = tanhf(in_ + r * hn);
    out[idx] = (1.0f - z) * nv + z * hin[idx];
}

// ---------------- launch ----------------
extern "C" void kernel_launch(void* const* d_in, const int* in_sizes, int n_in,
                              void* d_out, int out_size) {
    const float* h_ptr = (const float*)d_in[0];
    const float* W     = (const float*)d_in[1];
    const float* a     = (const float*)d_in[2];
    const float* W_ih  = (const float*)d_in[3];
    const float* W_hh  = (const float*)d_in[4];
    const float* b_ih  = (const float*)d_in[5];
    const float* b_hh  = (const float*)d_in[6];
    const int*   src   = (const int*)d_in[7];
    const int*   dst   = (const int*)d_in[8];
    float* out = (float*)d_out;
    (void)in_sizes; (void)n_in; (void)out_size;

    // CSR build + W transpose
    k_init_counts<<<(N_NODES + 255) / 256, 256>>>();
    k_count<<<(N_EDGES + 255) / 256, 256>>>(dst);
    k_transposeW<<<(H * D * D + 255) / 256, 256>>>(W);
    k_scan<<<1, 1024>>>();
    k_fill<<<(N_EDGES + 255) / 256, 256>>>(dst);

    // Wh = h @ W[h]  (wmma bf16 3-term, pipelined)
    dim3 g1(N_NODES / 128, H);
    k_wh_tc<<<g1, 256>>>(h_ptr);

    // attention scores
    k_scores<<<(N_NODES * H) / 8, 256>>>(a);

    // softmax-aggregate into h'
    k_agg<<<N_NODES, 128>>>(src);

    // gi = x @ W_ih^T
    dim3 g2(N_NODES / 128, 3);
    k_gi_tc<<<g2, 256>>>(W_ih);

    // gh = h @ W_hh^T
    k_gh_tc<<<g2, 256>>>(h_ptr, W_hh);

    // GRU combine (+ biases)
    k_gru<<<(N_NODES * D + 255) / 256, 256>>>(h_ptr, b_ih, b_hh, out);
}

// round 12
// speedup vs baseline: 1.1247x; 1.1247x over previous
#include <cuda_runtime.h>
#include <cuda_bf16.h>
#include <mma.h>
#include <math.h>
#include <stdint.h>

using namespace nvcuda;

#define N_NODES 16000
#define N_EDGES 256000
#define D 128
#define H 4
#define G3 (3*D)        // 384
#define HD (H*D)        // 512
#define ALPHA 0.2f

// ---------------- static scratch ----------------
__device__ float g_Wh[N_NODES * H * D];
__device__ float g_ssrc[N_NODES * H];
__device__ float g_sdst[N_NODES * H];
__device__ float g_hprime[N_NODES * H * D];   // x reshaped (N, 512)
__device__ float g_gi[N_NODES * G3];
__device__ float g_gh[N_NODES * G3];
__device__ float g_WT[H * D * D];             // W transposed: [h][e][d]
__device__ __align__(16) int g_deg[N_NODES];
__device__ int   g_fill[N_NODES];
__device__ __align__(16) int g_rowptr[N_NODES + 4];
__device__ int   g_esrc[N_EDGES];             // src node id per CSR slot

// split fp32 -> bf16 hi + bf16 lo
__device__ __forceinline__ void split1(float x, __nv_bfloat16& hi, __nv_bfloat16& lo) {
    hi = __float2bfloat16_rn(x);
    lo = __float2bfloat16_rn(x - __bfloat162float(hi));
}

// ---------------- wmma GEMM (R6 mainloop): C[128 x 128-tile] = A[M,K] @ B[NB,K]^T --------
// 3-term bf16 split: C = Ah*Bh + Ah*Bl + Al*Bh  (fp32 accum)
// 256 threads = 8 warps, warp grid 4(m) x 2(n), warp tile 32x64.
template<int KTOT>
__device__ __forceinline__ void tc_gemm_wmma(const float* __restrict__ A,
                                             const float* __restrict__ B,
                                             float* __restrict__ C, int ldC) {
    __shared__ __nv_bfloat16 Ah[128][40];
    __shared__ __nv_bfloat16 Al[128][40];
    __shared__ __nv_bfloat16 Bh[128][40];
    __shared__ __nv_bfloat16 Bl[128][40];

    int tid = threadIdx.x;
    int wid = tid >> 5;
    int warpM = wid >> 1;          // 0..3
    int warpN = wid & 1;           // 0..1
    int row0 = blockIdx.x * 128;

    wmma::fragment<wmma::accumulator, 16, 16, 16, float> acc[2][4];
    #pragma unroll
    for (int i = 0; i < 2; i++)
        #pragma unroll
        for (int j = 0; j < 4; j++)
            wmma::fill_fragment(acc[i][j], 0.0f);

    const int KC = KTOT / 32;
    for (int c = 0; c < KC; c++) {
        #pragma unroll
        for (int it = 0; it < 4; it++) {
            int idx = tid + it * 256;
            int r = idx >> 3;
            int c4 = (idx & 7) * 4;
            float4 v = *(const float4*)&A[(size_t)(row0 + r) * KTOT + c * 32 + c4];
            split1(v.x, Ah[r][c4 + 0], Al[r][c4 + 0]);
            split1(v.y, Ah[r][c4 + 1], Al[r][c4 + 1]);
            split1(v.z, Ah[r][c4 + 2], Al[r][c4 + 2]);
            split1(v.w, Ah[r][c4 + 3], Al[r][c4 + 3]);
        }
        #pragma unroll
        for (int it = 0; it < 4; it++) {
            int idx = tid + it * 256;
            int r = idx >> 3;
            int c4 = (idx & 7) * 4;
            float4 v = *(const float4*)&B[(size_t)r * KTOT + c * 32 + c4];
            split1(v.x, Bh[r][c4 + 0], Bl[r][c4 + 0]);
            split1(v.y, Bh[r][c4 + 1], Bl[r][c4 + 1]);
            split1(v.z, Bh[r][c4 + 2], Bl[r][c4 + 2]);
            split1(v.w, Bh[r][c4 + 3], Bl[r][c4 + 3]);
        }
        __syncthreads();

        #pragma unroll
        for (int ks = 0; ks < 2; ks++) {
            wmma::fragment<wmma::matrix_a, 16, 16, 16, __nv_bfloat16, wmma::row_major> a_hi[2], a_lo[2];
            #pragma unroll
            for (int fm = 0; fm < 2; fm++) {
                wmma::load_matrix_sync(a_hi[fm], &Ah[warpM * 32 + fm * 16][ks * 16], 40);
                wmma::load_matrix_sync(a_lo[fm], &Al[warpM * 32 + fm * 16][ks * 16], 40);
            }
            #pragma unroll
            for (int fn = 0; fn < 4; fn++) {
                wmma::fragment<wmma::matrix_b, 16, 16, 16, __nv_bfloat16, wmma::col_major> b_hi, b_lo;
                wmma::load_matrix_sync(b_hi, &Bh[warpN * 64 + fn * 16][ks * 16], 40);
                wmma::load_matrix_sync(b_lo, &Bl[warpN * 64 + fn * 16][ks * 16], 40);
                #pragma unroll
                for (int fm = 0; fm < 2; fm++) {
                    wmma::mma_sync(acc[fm][fn], a_hi[fm], b_hi, acc[fm][fn]);
                    wmma::mma_sync(acc[fm][fn], a_hi[fm], b_lo, acc[fm][fn]);
                    wmma::mma_sync(acc[fm][fn], a_lo[fm], b_hi, acc[fm][fn]);
                }
            }
        }
        __syncthreads();
    }

    #pragma unroll
    for (int fm = 0; fm < 2; fm++) {
        int row = row0 + warpM * 32 + fm * 16;
        #pragma unroll
        for (int fn = 0; fn < 4; fn++) {
            int col = warpN * 64 + fn * 16;
            wmma::store_matrix_sync(&C[(size_t)row * ldC + col], acc[fm][fn], ldC, wmma::mem_row_major);
        }
    }
}

__global__ void __launch_bounds__(256) k_wh_tc(const float* __restrict__ hin) {
    int head = blockIdx.y;
    tc_gemm_wmma<128>(hin, &g_WT[head << 14], &g_Wh[head << 7], HD);
}
__global__ void __launch_bounds__(256) k_gi_tc(const float* __restrict__ Wih) {
    int col0 = blockIdx.y * 128;
    tc_gemm_wmma<HD>(g_hprime, Wih + (size_t)col0 * HD, g_gi + col0, G3);
}
__global__ void __launch_bounds__(256) k_gh_tc(const float* __restrict__ hin,
                                               const float* __restrict__ Whh) {
    int col0 = blockIdx.y * 128;
    tc_gemm_wmma<D>(hin, Whh + (size_t)col0 * D, g_gh + col0, G3);
}

// ---------------- init: zero counters + transpose W (one launch) ----------------
__global__ void k_init(const float* __restrict__ W) {
    int i = blockIdx.x * blockDim.x + threadIdx.x;
    if (i < N_NODES) { g_deg[i] = 0; g_fill[i] = 0; }
    if (i < H * D * D) {
        int h = i >> 14, rem = i & 16383, d = rem >> 7, e = rem & 127;
        g_WT[(h << 14) + (e << 7) + d] = W[i];
    }
}

__global__ void k_count(const int* __restrict__ dst) {
    int e = blockIdx.x * blockDim.x + threadIdx.x;
    if (e < N_EDGES) atomicAdd(&g_deg[dst[e]], 1);
}

// fast single-block scan: 1000 active thr x 16 elems (int4), warp-shuffle based
__global__ void __launch_bounds__(1024) k_scan() {
    __shared__ int wsum[32];
    int t = threadIdx.x;
    int lane = t & 31, warp = t >> 5;
    bool active = t < 1000;
    int v[16];
    int s = 0;
    if (active) {
        const int4* d4 = (const int4*)g_deg;
        #pragma unroll
        for (int i = 0; i < 4; i++) {
            int4 x = d4[t * 4 + i];
            v[i * 4 + 0] = s; s += x.x;
            v[i * 4 + 1] = s; s += x.y;
            v[i * 4 + 2] = s; s += x.z;
            v[i * 4 + 3] = s; s += x.w;
        }
    }
    int incl = s;
    #pragma unroll
    for (int o = 1; o < 32; o <<= 1) {
        int y = __shfl_up_sync(0xffffffffu, incl, o);
        if (lane >= o) incl += y;
    }
    if (lane == 31) wsum[warp] = incl;
    __syncthreads();
    if (warp == 0) {
        int w = wsum[lane];
        #pragma unroll
        for (int o = 1; o < 32; o <<= 1) {
            int y = __shfl_up_sync(0xffffffffu, w, o);
            if (lane >= o) w += y;
        }
        wsum[lane] = w;
    }
    __syncthreads();
    int warpoff = (warp > 0) ? wsum[warp - 1] : 0;
    int throff = warpoff + (incl - s);
    if (active) {
        int4* r4 = (int4*)g_rowptr;
        #pragma unroll
        for (int i = 0; i < 4; i++)
            r4[t * 4 + i] = make_int4(throff + v[i * 4 + 0], throff + v[i * 4 + 1],
                                      throff + v[i * 4 + 2], throff + v[i * 4 + 3]);
    }
    if (t == 1023) g_rowptr[N_NODES] = wsum[31];
}

// fill: store SRC NODE ID per CSR slot (kills one indirection in agg)
__global__ void k_fill(const int* __restrict__ src, const int* __restrict__ dst) {
    int e = blockIdx.x * blockDim.x + threadIdx.x;
    if (e < N_EDGES) {
        int d = dst[e];
        int pos = g_rowptr[d] + atomicAdd(&g_fill[d], 1);
        g_esrc[pos] = src[e];
    }
}

// ---------------- scores ----------------
__global__ void __launch_bounds__(256) k_scores(const float* __restrict__ a) {
    int tid = threadIdx.x, lane = tid & 31, warp = tid >> 5;
    int w = blockIdx.x * 8 + warp;
    int head = w & (H - 1);
    float4 wv = ((const float4*)(g_Wh + w * D))[lane];
    float4 a1 = *(const float4*)&a[head * (2 * D) + lane * 4];
    float4 a2 = *(const float4*)&a[head * (2 * D) + D + lane * 4];
    float d1 = wv.x * a1.x + wv.y * a1.y + wv.z * a1.z + wv.w * a1.w;
    float d2 = wv.x * a2.x + wv.y * a2.y + wv.z * a2.z + wv.w * a2.w;
    #pragma unroll
    for (int o = 16; o; o >>= 1) {
        d1 += __shfl_xor_sync(0xffffffffu, d1, o);
        d2 += __shfl_xor_sync(0xffffffffu, d2, o);
    }
    if (lane == 0) { g_ssrc[w] = d1; g_sdst[w] = d2; }
}

// ---------------- single-pass online-softmax aggregate ----------------
__global__ void __launch_bounds__(128) k_agg() {
    int n = blockIdx.x;
    int head = threadIdx.x >> 5;
    int lane = threadIdx.x & 31;
    int start = g_rowptr[n], end = g_rowptr[n + 1];
    float4 acc = make_float4(0.f, 0.f, 0.f, 0.f);
    if (end > start) {
        float sd = g_sdst[n * H + head];
        float m = -1e30f, sum = 0.f;
        for (int jb = start; jb < end; jb += 32) {
            int myidx = jb + lane;
            int s_pre = 0;
            float v_pre = 0.f;
            if (myidx < end) {
                s_pre = g_esrc[myidx];                 // coalesced
                v_pre = g_ssrc[s_pre * H + head];      // parallel gather (MLP 32)
            }
            int cnt = min(32, end - jb);
            for (int t = 0; t < cnt; t++) {
                int s = __shfl_sync(0xffffffffu, s_pre, t);
                float v = __shfl_sync(0xffffffffu, v_pre, t) + sd;
                v = v >= 0.f ? v : ALPHA * v;
                float scale = 1.f;
                if (v > m) { scale = __expf(m - v); m = v; }
                float att = __expf(v - m);
                float4 wv = ((const float4*)(g_Wh + (s * H + head) * D))[lane];
                sum = sum * scale + att;
                acc.x = fmaf(att, wv.x, acc.x * scale);
                acc.y = fmaf(att, wv.y, acc.y * scale);
                acc.z = fmaf(att, wv.z, acc.z * scale);
                acc.w = fmaf(att, wv.w, acc.w * scale);
            }
        }
        float inv = 1.0f / sum;
        acc.x *= inv; acc.y *= inv; acc.z *= inv; acc.w *= inv;
    }
    ((float4*)(g_hprime + (n * H + head) * D))[lane] = acc;
}

// ---------------- GRU elementwise (bias folded here) ----------------
__global__ void __launch_bounds__(256) k_gru(const float* __restrict__ hin,
                                             const float* __restrict__ bih,
                                             const float* __restrict__ bhh,
                                             float* __restrict__ out) {
    int idx = blockIdx.x * blockDim.x + threadIdx.x;
    if (idx >= N_NODES * D) return;
    int n = idx >> 7;
    int d = idx & (D - 1);
    float ir = g_gi[n * G3 + d]          + bih[d];
    float iz = g_gi[n * G3 + D + d]      + bih[D + d];
    float in_ = g_gi[n * G3 + 2 * D + d] + bih[2 * D + d];
    float hr = g_gh[n * G3 + d]          + bhh[d];
    float hz = g_gh[n * G3 + D + d]      + bhh[D + d];
    float hn = g_gh[n * G3 + 2 * D + d]  + bhh[2 * D + d];
    float r = 1.0f / (1.0f + __expf(-(ir + hr)));
    float z = 1.0f / (1.0f + __expf(-(iz + hz)));
    float nv = tanhf(in_ + r * hn);
    out[idx] = (1.0f - z) * nv + z * hin[idx];
}

// ---------------- launch ----------------
extern "C" void kernel_launch(void* const* d_in, const int* in_sizes, int n_in,
                              void* d_out, int out_size) {
    const float* h_ptr = (const float*)d_in[0];
    const float* W     = (const float*)d_in[1];
    const float* a     = (const float*)d_in[2];
    const float* W_ih  = (const float*)d_in[3];
    const float* W_hh  = (const float*)d_in[4];
    const float* b_ih  = (const float*)d_in[5];
    const float* b_hh  = (const float*)d_in[6];
    const int*   src   = (const int*)d_in[7];
    const int*   dst   = (const int*)d_in[8];
    float* out = (float*)d_out;
    (void)in_sizes; (void)n_in; (void)out_size;

    // init (zero counters + W transpose), CSR build
    k_init<<<(H * D * D + 255) / 256, 256>>>(W);
    k_count<<<(N_EDGES + 255) / 256, 256>>>(dst);
    k_scan<<<1, 1024>>>();
    k_fill<<<(N_EDGES + 255) / 256, 256>>>(src, dst);

    // Wh = h @ W[h]  (wmma bf16 3-term)
    dim3 g1(N_NODES / 128, H);
    k_wh_tc<<<g1, 256>>>(h_ptr);

    // attention scores
    k_scores<<<(N_NODES * H) / 8, 256>>>(a);

    // single-pass softmax-aggregate into h'
    k_agg<<<N_NODES, 128>>>();

    // gi = x @ W_ih^T
    dim3 g2(N_NODES / 128, 3);
    k_gi_tc<<<g2, 256>>>(W_ih);

    // gh = h @ W_hh^T
    k_gh_tc<<<g2, 256>>>(h_ptr, W_hh);

    // GRU combine (+ biases)
    k_gru<<<(N_NODES * D + 255) / 256, 256>>>(h_ptr, b_ih, b_hh, out);
}

// round 15
// speedup vs baseline: 1.3249x; 1.1781x over previous
#include <cuda_runtime.h>
#include <cuda_bf16.h>
#include <mma.h>
#include <math.h>
#include <stdint.h>

using namespace nvcuda;

#define N_NODES 16000
#define N_EDGES 256000
#define D 128
#define H 4
#define G3 (3*D)        // 384
#define HD (H*D)        // 512
#define ALPHA 0.2f

// ---------------- static scratch ----------------
__device__ float g_Wh[N_NODES * H * D];
__device__ float g_ssrc[N_NODES * H];
__device__ float g_sdst[N_NODES * H];
__device__ float g_hprime[N_NODES * H * D];   // x reshaped (N, 512)
__device__ float g_gi[N_NODES * G3];
__device__ float g_gh[N_NODES * G3];
__device__ float g_WT[H * D * D];             // W transposed: [h][e][d]
__device__ __align__(16) int g_deg[N_NODES];
__device__ int   g_fill[N_NODES];
__device__ __align__(16) int g_rowptr[N_NODES + 4];
__device__ int   g_esrc[N_EDGES];             // src node id per CSR slot

// ---------------- helpers ----------------
__device__ __forceinline__ uint32_t smem_u32(const void* p) {
    uint32_t a;
    asm("{ .reg .u64 t; cvta.to.shared.u64 t, %1; cvt.u32.u64 %0, t; }" : "=r"(a) : "l"(p));
    return a;
}
__device__ __forceinline__ void cp16(uint32_t dst, const void* src) {
    asm volatile("cp.async.cg.shared.global [%0], [%1], 16;" :: "r"(dst), "l"(src));
}
#define CP_COMMIT() asm volatile("cp.async.commit_group;" ::: "memory")
#define CP_WAIT0()  asm volatile("cp.async.wait_group 0;" ::: "memory")

// split fp32 -> bf16 hi + bf16 lo
__device__ __forceinline__ void split1(float x, __nv_bfloat16& hi, __nv_bfloat16& lo) {
    hi = __float2bfloat16_rn(x);
    lo = __float2bfloat16_rn(x - __bfloat162float(hi));
}

// ---------------- cp.async-pipelined wmma GEMM ----------------
// C[128 x 128-tile] = A[M,K] @ B[NB,K]^T, 3-term bf16 split (fp32 accum).
// 256 threads = 8 warps, warp grid 4(m) x 2(n), warp tile 32x64.
// Dynamic smem layout (bytes):
//   STA 0      : stage A fp32 [128][32] (16384)
//   STB 16384  : stage B fp32 [128][32] (16384)
//   AH  32768  : bf16 [128][40] (10240)
//   AL  43008, BH 53248, BL 63488   -> total 73728
#define SMEM_GEMM 73728
template<int KTOT>
__device__ __forceinline__ void tc_gemm_wmma(const float* __restrict__ A,
                                             const float* __restrict__ B,
                                             float* __restrict__ C, int ldC) {
    extern __shared__ char sm[];
    float* stA = (float*)sm;
    float* stB = (float*)(sm + 16384);
    __nv_bfloat16* Ah = (__nv_bfloat16*)(sm + 32768);
    __nv_bfloat16* Al = (__nv_bfloat16*)(sm + 43008);
    __nv_bfloat16* Bh = (__nv_bfloat16*)(sm + 53248);
    __nv_bfloat16* Bl = (__nv_bfloat16*)(sm + 63488);
    uint32_t stA_u = smem_u32(stA), stB_u = smem_u32(stB);

    int tid = threadIdx.x;
    int wid = tid >> 5;
    int warpM = wid >> 1;          // 0..3
    int warpN = wid & 1;           // 0..1
    int row0 = blockIdx.x * 128;

    wmma::fragment<wmma::accumulator, 16, 16, 16, float> acc[2][4];
    #pragma unroll
    for (int i = 0; i < 2; i++)
        #pragma unroll
        for (int j = 0; j < 4; j++)
            wmma::fill_fragment(acc[i][j], 0.0f);

    const int KC = KTOT / 32;

    // preload chunk 0 (A and B: 1024 16B segments each, 4 per thread)
    #pragma unroll
    for (int it = 0; it < 4; it++) {
        int idx = tid + it * 256;
        int r = idx >> 3, seg = idx & 7;
        cp16(stA_u + idx * 16, &A[(size_t)(row0 + r) * KTOT + seg * 4]);
        cp16(stB_u + idx * 16, &B[(size_t)r * KTOT + seg * 4]);
    }
    CP_COMMIT();
    CP_WAIT0();
    __syncthreads();

    #pragma unroll 1
    for (int c = 0; c < KC; c++) {
        // convert stage -> bf16 tiles
        #pragma unroll
        for (int it = 0; it < 4; it++) {
            int idx = tid + it * 256;
            int r = idx >> 3, c4 = (idx & 7) * 4;
            float4 va = *(const float4*)&stA[r * 32 + c4];
            float4 vb = *(const float4*)&stB[r * 32 + c4];
            int o = r * 40 + c4;
            split1(va.x, Ah[o + 0], Al[o + 0]);
            split1(va.y, Ah[o + 1], Al[o + 1]);
            split1(va.z, Ah[o + 2], Al[o + 2]);
            split1(va.w, Ah[o + 3], Al[o + 3]);
            split1(vb.x, Bh[o + 0], Bl[o + 0]);
            split1(vb.y, Bh[o + 1], Bl[o + 1]);
            split1(vb.z, Bh[o + 2], Bl[o + 2]);
            split1(vb.w, Bh[o + 3], Bl[o + 3]);
        }
        __syncthreads();   // tiles ready; stage free

        // issue async loads for next chunk (overlap the MMA phase)
        if (c + 1 < KC) {
            #pragma unroll
            for (int it = 0; it < 4; it++) {
                int idx = tid + it * 256;
                int r = idx >> 3, seg = idx & 7;
                cp16(stA_u + idx * 16, &A[(size_t)(row0 + r) * KTOT + (c + 1) * 32 + seg * 4]);
                cp16(stB_u + idx * 16, &B[(size_t)r * KTOT + (c + 1) * 32 + seg * 4]);
            }
            CP_COMMIT();
        }

        // MMA phase on chunk c
        #pragma unroll
        for (int ks = 0; ks < 2; ks++) {
            wmma::fragment<wmma::matrix_a, 16, 16, 16, __nv_bfloat16, wmma::row_major> a_hi[2], a_lo[2];
            #pragma unroll
            for (int fm = 0; fm < 2; fm++) {
                a_hi[fm].x[0] = 0; a_lo[fm].x[0] = 0; // silence un-init warnings (overwritten)
                wmma::load_matrix_sync(a_hi[fm], &Ah[(warpM * 32 + fm * 16) * 40 + ks * 16], 40);
                wmma::load_matrix_sync(a_lo[fm], &Al[(warpM * 32 + fm * 16) * 40 + ks * 16], 40);
            }
            #pragma unroll
            for (int fn = 0; fn < 4; fn++) {
                wmma::fragment<wmma::matrix_b, 16, 16, 16, __nv_bfloat16, wmma::col_major> b_hi, b_lo;
                wmma::load_matrix_sync(b_hi, &Bh[(warpN * 64 + fn * 16) * 40 + ks * 16], 40);
                wmma::load_matrix_sync(b_lo, &Bl[(warpN * 64 + fn * 16) * 40 + ks * 16], 40);
                #pragma unroll
                for (int fm = 0; fm < 2; fm++) {
                    wmma::mma_sync(acc[fm][fn], a_hi[fm], b_hi, acc[fm][fn]);
                    wmma::mma_sync(acc[fm][fn], a_hi[fm], b_lo, acc[fm][fn]);
                    wmma::mma_sync(acc[fm][fn], a_lo[fm], b_hi, acc[fm][fn]);
                }
            }
        }
        if (c + 1 < KC) CP_WAIT0();
        __syncthreads();   // MMA reads done (tiles free); stage filled
    }

    #pragma unroll
    for (int fm = 0; fm < 2; fm++) {
        int row = row0 + warpM * 32 + fm * 16;
        #pragma unroll
        for (int fn = 0; fn < 4; fn++) {
            int col = warpN * 64 + fn * 16;
            wmma::store_matrix_sync(&C[(size_t)row * ldC + col], acc[fm][fn], ldC, wmma::mem_row_major);
        }
    }
}

__global__ void __launch_bounds__(256) k_wh_tc(const float* __restrict__ hin) {
    int head = blockIdx.y;
    tc_gemm_wmma<128>(hin, &g_WT[head << 14], &g_Wh[head << 7], HD);
}
__global__ void __launch_bounds__(256) k_gi_tc(const float* __restrict__ Wih) {
    int col0 = blockIdx.y * 128;
    tc_gemm_wmma<HD>(g_hprime, Wih + (size_t)col0 * HD, g_gi + col0, G3);
}
__global__ void __launch_bounds__(256) k_gh_tc(const float* __restrict__ hin,
                                               const float* __restrict__ Whh) {
    int col0 = blockIdx.y * 128;
    tc_gemm_wmma<D>(hin, Whh + (size_t)col0 * D, g_gh + col0, G3);
}

// ---------------- init: zero counters + transpose W (one launch) ----------------
__global__ void k_init(const float* __restrict__ W) {
    int i = blockIdx.x * blockDim.x + threadIdx.x;
    if (i < N_NODES) { g_deg[i] = 0; g_fill[i] = 0; }
    if (i < H * D * D) {
        int h = i >> 14, rem = i & 16383, d = rem >> 7, e = rem & 127;
        g_WT[(h << 14) + (e << 7) + d] = W[i];
    }
}

__global__ void k_count(const int* __restrict__ dst) {
    int e = blockIdx.x * blockDim.x + threadIdx.x;
    if (e < N_EDGES) atomicAdd(&g_deg[dst[e]], 1);
}

// fast single-block scan: 1000 active thr x 16 elems (int4), warp-shuffle based
__global__ void __launch_bounds__(1024) k_scan() {
    __shared__ int wsum[32];
    int t = threadIdx.x;
    int lane = t & 31, warp = t >> 5;
    bool active = t < 1000;
    int v[16];
    int s = 0;
    if (active) {
        const int4* d4 = (const int4*)g_deg;
        #pragma unroll
        for (int i = 0; i < 4; i++) {
            int4 x = d4[t * 4 + i];
            v[i * 4 + 0] = s; s += x.x;
            v[i * 4 + 1] = s; s += x.y;
            v[i * 4 + 2] = s; s += x.z;
            v[i * 4 + 3] = s; s += x.w;
        }
    }
    int incl = s;
    #pragma unroll
    for (int o = 1; o < 32; o <<= 1) {
        int y = __shfl_up_sync(0xffffffffu, incl, o);
        if (lane >= o) incl += y;
    }
    if (lane == 31) wsum[warp] = incl;
    __syncthreads();
    if (warp == 0) {
        int w = wsum[lane];
        #pragma unroll
        for (int o = 1; o < 32; o <<= 1) {
            int y = __shfl_up_sync(0xffffffffu, w, o);
            if (lane >= o) w += y;
        }
        wsum[lane] = w;
    }
    __syncthreads();
    int warpoff = (warp > 0) ? wsum[warp - 1] : 0;
    int throff = warpoff + (incl - s);
    if (active) {
        int4* r4 = (int4*)g_rowptr;
        #pragma unroll
        for (int i = 0; i < 4; i++)
            r4[t * 4 + i] = make_int4(throff + v[i * 4 + 0], throff + v[i * 4 + 1],
                                      throff + v[i * 4 + 2], throff + v[i * 4 + 3]);
    }
    if (t == 1023) g_rowptr[N_NODES] = wsum[31];
}

// fill: store SRC NODE ID per CSR slot
__global__ void k_fill(const int* __restrict__ src, const int* __restrict__ dst) {
    int e = blockIdx.x * blockDim.x + threadIdx.x;
    if (e < N_EDGES) {
        int d = dst[e];
        int pos = g_rowptr[d] + atomicAdd(&g_fill[d], 1);
        g_esrc[pos] = src[e];
    }
}

// ---------------- scores ----------------
__global__ void __launch_bounds__(256) k_scores(const float* __restrict__ a) {
    int tid = threadIdx.x, lane = tid & 31, warp = tid >> 5;
    int w = blockIdx.x * 8 + warp;
    int head = w & (H - 1);
    float4 wv = ((const float4*)(g_Wh + w * D))[lane];
    float4 a1 = *(const float4*)&a[head * (2 * D) + lane * 4];
    float4 a2 = *(const float4*)&a[head * (2 * D) + D + lane * 4];
    float d1 = wv.x * a1.x + wv.y * a1.y + wv.z * a1.z + wv.w * a1.w;
    float d2 = wv.x * a2.x + wv.y * a2.y + wv.z * a2.z + wv.w * a2.w;
    #pragma unroll
    for (int o = 16; o; o >>= 1) {
        d1 += __shfl_xor_sync(0xffffffffu, d1, o);
        d2 += __shfl_xor_sync(0xffffffffu, d2, o);
    }
    if (lane == 0) { g_ssrc[w] = d1; g_sdst[w] = d2; }
}

// ---------------- single-pass online-softmax aggregate ----------------
__global__ void __launch_bounds__(128) k_agg() {
    int n = blockIdx.x;
    int head = threadIdx.x >> 5;
    int lane = threadIdx.x & 31;
    int start = g_rowptr[n], end = g_rowptr[n + 1];
    float4 acc = make_float4(0.f, 0.f, 0.f, 0.f);
    if (end > start) {
        float sd = g_sdst[n * H + head];
        float m = -1e30f, sum = 0.f;
        for (int jb = start; jb < end; jb += 32) {
            int myidx = jb + lane;
            int s_pre = 0;
            float v_pre = 0.f;
            if (myidx < end) {
                s_pre = g_esrc[myidx];
                v_pre = g_ssrc[s_pre * H + head];
            }
            int cnt = min(32, end - jb);
            for (int t = 0; t < cnt; t++) {
                int s = __shfl_sync(0xffffffffu, s_pre, t);
                float v = __shfl_sync(0xffffffffu, v_pre, t) + sd;
                v = v >= 0.f ? v : ALPHA * v;
                float scale = 1.f;
                if (v > m) { scale = __expf(m - v); m = v; }
                float att = __expf(v - m);
                float4 wv = ((const float4*)(g_Wh + (s * H + head) * D))[lane];
                sum = sum * scale + att;
                acc.x = fmaf(att, wv.x, acc.x * scale);
                acc.y = fmaf(att, wv.y, acc.y * scale);
                acc.z = fmaf(att, wv.z, acc.z * scale);
                acc.w = fmaf(att, wv.w, acc.w * scale);
            }
        }
        float inv = 1.0f / sum;
        acc.x *= inv; acc.y *= inv; acc.z *= inv; acc.w *= inv;
    }
    ((float4*)(g_hprime + (n * H + head) * D))[lane] = acc;
}

// ---------------- GRU elementwise (bias folded here) ----------------
__global__ void __launch_bounds__(256) k_gru(const float* __restrict__ hin,
                                             const float* __restrict__ bih,
                                             const float* __restrict__ bhh,
                                             float* __restrict__ out) {
    int idx = blockIdx.x * blockDim.x + threadIdx.x;
    if (idx >= N_NODES * D) return;
    int n = idx >> 7;
    int d = idx & (D - 1);
    float ir = g_gi[n * G3 + d]          + bih[d];
    float iz = g_gi[n * G3 + D + d]      + bih[D + d];
    float in_ = g_gi[n * G3 + 2 * D + d] + bih[2 * D + d];
    float hr = g_gh[n * G3 + d]          + bhh[d];
    float hz = g_gh[n * G3 + D + d]      + bhh[D + d];
    float hn = g_gh[n * G3 + 2 * D + d]  + bhh[2 * D + d];
    float r = 1.0f / (1.0f + __expf(-(ir + hr)));
    float z = 1.0f / (1.0f + __expf(-(iz + hz)));
    float nv = tanhf(in_ + r * hn);
    out[idx] = (1.0f - z) * nv + z * hin[idx];
}

// ---------------- launch ----------------
extern "C" void kernel_launch(void* const* d_in, const int* in_sizes, int n_in,
                              void* d_out, int out_size) {
    const float* h_ptr = (const float*)d_in[0];
    const float* W     = (const float*)d_in[1];
    const float* a     = (const float*)d_in[2];
    const float* W_ih  = (const float*)d_in[3];
    const float* W_hh  = (const float*)d_in[4];
    const float* b_ih  = (const float*)d_in[5];
    const float* b_hh  = (const float*)d_in[6];
    const int*   src   = (const int*)d_in[7];
    const int*   dst   = (const int*)d_in[8];
    float* out = (float*)d_out;
    (void)in_sizes; (void)n_in; (void)out_size;

    cudaFuncSetAttribute(k_wh_tc, cudaFuncAttributeMaxDynamicSharedMemorySize, SMEM_GEMM);
    cudaFuncSetAttribute(k_gi_tc, cudaFuncAttributeMaxDynamicSharedMemorySize, SMEM_GEMM);
    cudaFuncSetAttribute(k_gh_tc, cudaFuncAttributeMaxDynamicSharedMemorySize, SMEM_GEMM);

    // init (zero counters + W transpose), CSR build
    k_init<<<(H * D * D + 255) / 256, 256>>>(W);
    k_count<<<(N_EDGES + 255) / 256, 256>>>(dst);
    k_scan<<<1, 1024>>>();
    k_fill<<<(N_EDGES + 255) / 256, 256>>>(src, dst);

    // Wh = h @ W[h]  (wmma bf16 3-term, cp.async pipelined)
    dim3 g1(N_NODES / 128, H);
    k_wh_tc<<<g1, 256, SMEM_GEMM>>>(h_ptr);

    // attention scores
    k_scores<<<(N_NODES * H) / 8, 256>>>(a);

    // single-pass softmax-aggregate into h'
    k_agg<<<N_NODES, 128>>>();

    // gi = x @ W_ih^T
    dim3 g2(N_NODES / 128, 3);
    k_gi_tc<<<g2, 256, SMEM_GEMM>>>(W_ih);

    // gh = h @ W_hh^T
    k_gh_tc<<<g2, 256, SMEM_GEMM>>>(h_ptr, W_hh);

    // GRU combine (+ biases)
    k_gru<<<(N_NODES * D + 255) / 256, 256>>>(h_ptr, b_ih, b_hh, out);
}